// round 3
// baseline (speedup 1.0000x reference)
#include <cuda_runtime.h>
#include <cstdint>

#define NN 100000
#define NE 1600000
#define DH 64
#define F1 256

typedef unsigned long long ull;

__device__ __forceinline__ ull pack2(float x) {
    ull r; asm("mov.b64 %0,{%1,%1};" : "=l"(r) : "f"(x)); return r;
}
__device__ __forceinline__ void ffma2(ull& d, ull a, ull b) {
    asm("fma.rn.f32x2 %0,%1,%2,%0;" : "+l"(d) : "l"(a), "l"(b));
}
__device__ __forceinline__ float2 unpack2(ull v) {
    float2 r; asm("mov.b64 {%0,%1},%2;" : "=f"(r.x), "=f"(r.y) : "l"(v)); return r;
}

// ---------------- scratch ----------------
__device__ int   g_deg[NN];
__device__ int   g_scan[NN];
__device__ int   g_bsum[128];
__device__ int   g_rowptr[NN + 1];
__device__ int   g_cursor[NN];
__device__ int   g_srcidx[NE];
__device__ float g_dinv[NN];
__device__ float g_h[NN * DH];      // GEMM output (pre-scaled by dinv)
__device__ float g_hagg[NN * DH];   // aggregation output
__device__ float g_ssq;

// ---------------- setup ----------------
__global__ void k_init(float* __restrict__ out, const float* __restrict__ b2) {
    int i = blockIdx.x * blockDim.x + threadIdx.x;
    if (i < NN) { g_deg[i] = 0; out[i] = b2[0]; }
    if (i == 0) g_ssq = 0.f;
}

__global__ void k_hist(const int* __restrict__ ei) {
    int e = blockIdx.x * blockDim.x + threadIdx.x;
    if (e < NE / 4) {
        int4 c = ((const int4*)(ei + NE))[e];
        atomicAdd(&g_deg[c.x], 1);
        atomicAdd(&g_deg[c.y], 1);
        atomicAdd(&g_deg[c.z], 1);
        atomicAdd(&g_deg[c.w], 1);
    }
}

__global__ void k_scan1() {
    __shared__ int s[1024];
    int i = blockIdx.x * 1024 + threadIdx.x;
    int v = (i < NN) ? g_deg[i] : 0;
    s[threadIdx.x] = v;
    __syncthreads();
    #pragma unroll
    for (int off = 1; off < 1024; off <<= 1) {
        int t = (threadIdx.x >= off) ? s[threadIdx.x - off] : 0;
        __syncthreads();
        s[threadIdx.x] += t;
        __syncthreads();
    }
    if (i < NN) g_scan[i] = s[threadIdx.x];
    if (threadIdx.x == 1023) g_bsum[blockIdx.x] = s[1023];
}

__global__ void k_scan2(int nb) {
    __shared__ int s[128];
    int t = threadIdx.x;
    int v = (t < nb) ? g_bsum[t] : 0;
    s[t] = v;
    __syncthreads();
    #pragma unroll
    for (int off = 1; off < 128; off <<= 1) {
        int u = (t >= off) ? s[t - off] : 0;
        __syncthreads();
        s[t] += u;
        __syncthreads();
    }
    if (t < nb) g_bsum[t] = s[t] - v;
}

__global__ void k_scan3() {
    int i = blockIdx.x * 1024 + threadIdx.x;
    if (i < NN) {
        int d = g_deg[i];
        int excl = g_scan[i] - d + g_bsum[blockIdx.x];
        g_rowptr[i] = excl;
        g_cursor[i] = excl;
        if (i == NN - 1) g_rowptr[NN] = excl + d;
        g_dinv[i] = rsqrtf((float)(d + 1));
    }
}

__global__ void k_csr(const int* __restrict__ ei) {
    int e = blockIdx.x * blockDim.x + threadIdx.x;
    if (e < NE / 4) {
        int4 r = ((const int4*)ei)[e];
        int4 c = ((const int4*)(ei + NE))[e];
        int p;
        p = atomicAdd(&g_cursor[c.x], 1); g_srcidx[p] = r.x;
        p = atomicAdd(&g_cursor[c.y], 1); g_srcidx[p] = r.y;
        p = atomicAdd(&g_cursor[c.z], 1); g_srcidx[p] = r.z;
        p = atomicAdd(&g_cursor[c.w], 1); g_srcidx[p] = r.w;
    }
}

// ---------------- GEMM: out[n][f] = dinv[n]*sum_k X[n][k]*W[k][f]  (W: 64x64) -------
// 256 threads, 128-node tile. X staged k-major (pairs contiguous); W staged as {w,w}.
// Per-thread 4 node-pairs x 4 f. Per k: 4 LDS.64 + 4 LDS.64 + 16 ffma2.
__global__ void __launch_bounds__(256) k_gemm(const float* __restrict__ X,
                                              const float* __restrict__ W,
                                              float* __restrict__ out) {
    extern __shared__ float sm[];
    ull*   ws2 = (ull*)sm;         // [64][64] duplicated pairs (32 KB)
    float* xs  = sm + 8192;        // [64][130] x transposed, pad 130 (33.3 KB)
    int tid = threadIdx.x;
    int nb = blockIdx.x * 128;

    for (int i = tid; i < 4096; i += 256) ws2[i] = pack2(W[i]);

    #pragma unroll
    for (int j = 0; j < 8; j++) {
        int lin = tid + j * 256;               // 2048 float4 slots
        int n = lin >> 4, k4 = (lin & 15) * 4;
        float4 v = make_float4(0.f, 0.f, 0.f, 0.f);
        if (nb + n < NN) v = *(const float4*)&X[(size_t)(nb + n) * DH + k4];
        xs[(k4 + 0) * 130 + n] = v.x;
        xs[(k4 + 1) * 130 + n] = v.y;
        xs[(k4 + 2) * 130 + n] = v.z;
        xs[(k4 + 3) * 130 + n] = v.w;
    }
    __syncthreads();

    int tx = tid & 15, ty = tid >> 4;
    int n0 = ty * 8;
    ull acc[4][4] = {};
    #pragma unroll 16
    for (int k = 0; k < 64; k++) {
        ull xp[4], wd[4];
        #pragma unroll
        for (int p = 0; p < 4; p++) xp[p] = *(const ull*)&xs[k * 130 + n0 + 2 * p];
        #pragma unroll
        for (int j = 0; j < 4; j++) wd[j] = ws2[k * 64 + tx + 16 * j];
        #pragma unroll
        for (int p = 0; p < 4; p++)
            #pragma unroll
            for (int j = 0; j < 4; j++) ffma2(acc[p][j], xp[p], wd[j]);
    }
    #pragma unroll
    for (int p = 0; p < 4; p++) {
        int n = nb + n0 + 2 * p;
        if (n < NN) {
            float slo = g_dinv[n];
            bool hi = (n + 1 < NN);
            float shi = hi ? g_dinv[n + 1] : 0.f;
            #pragma unroll
            for (int j = 0; j < 4; j++) {
                float2 t = unpack2(acc[p][j]);
                out[(size_t)n * DH + tx + 16 * j] = t.x * slo;
                if (hi) out[(size_t)(n + 1) * DH + tx + 16 * j] = t.y * shi;
            }
        }
    }
}

// ---------------- Aggregation (fp32): out[n]=relu(dinv[n]*(h[n]+sum h[src])+b) ------
__global__ void __launch_bounds__(256) k_agg(const float* __restrict__ hs,
                                             const float* __restrict__ bias,
                                             float* __restrict__ out) {
    int warp = (blockIdx.x * blockDim.x + threadIdx.x) >> 5;
    int lane = threadIdx.x & 31;
    if (warp >= NN) return;
    int n = warp;
    int f0 = lane * 2;

    float2 acc = *(const float2*)&hs[(size_t)n * DH + f0];   // self-loop term
    int beg = g_rowptr[n], end = g_rowptr[n + 1];
    for (int j = beg; j < end; j += 32) {
        int cnt = min(32, end - j);
        int s = (j + lane < end) ? g_srcidx[j + lane] : 0;
        #pragma unroll 4
        for (int t = 0; t < cnt; t++) {
            int ss = __shfl_sync(0xffffffffu, s, t);
            float2 v = *(const float2*)&hs[(size_t)ss * DH + f0];
            acc.x += v.x; acc.y += v.y;
        }
    }
    float d = g_dinv[n];
    float ox = fmaxf(fmaf(acc.x, d, bias[f0]), 0.f);
    float oy = fmaxf(fmaf(acc.y, d, bias[f0 + 1]), 0.f);
    *(float2*)&out[(size_t)n * DH + f0] = make_float2(ox, oy);
}

// ---------------- Fused MLP head as GEMM -------------------------------------------
// Block = 128 nodes x 64-f chunk (4 chunks). Same inner loop as k_gemm.
// Epilogue: relu(acc+b1)*w2, reduce over the 64 f of this chunk, atomicAdd partials.
__global__ void __launch_bounds__(256) k_fc(const float* __restrict__ H,
                                            const float* __restrict__ W1f,
                                            const float* __restrict__ b1f,
                                            const float* __restrict__ w2,
                                            float* __restrict__ out) {
    extern __shared__ float sm[];
    ull*   ws2 = (ull*)sm;         // [64][64] this f-chunk, duplicated
    float* xs  = sm + 8192;        // [64][130]
    int tid = threadIdx.x;
    int bid = blockIdx.x;
    int nb = (bid >> 2) * 128;
    int fbase = (bid & 3) * 64;

    for (int i = tid; i < 4096; i += 256) {
        int k = i >> 6, f = i & 63;
        ws2[i] = pack2(W1f[k * F1 + fbase + f]);
    }
    #pragma unroll
    for (int j = 0; j < 8; j++) {
        int lin = tid + j * 256;
        int n = lin >> 4, k4 = (lin & 15) * 4;
        float4 v = make_float4(0.f, 0.f, 0.f, 0.f);
        if (nb + n < NN) v = *(const float4*)&H[(size_t)(nb + n) * DH + k4];
        xs[(k4 + 0) * 130 + n] = v.x;
        xs[(k4 + 1) * 130 + n] = v.y;
        xs[(k4 + 2) * 130 + n] = v.z;
        xs[(k4 + 3) * 130 + n] = v.w;
    }
    __syncthreads();

    int tx = tid & 15, ty = tid >> 4;
    int n0 = ty * 8;
    ull acc[4][4] = {};
    #pragma unroll 16
    for (int k = 0; k < 64; k++) {
        ull xp[4], wd[4];
        #pragma unroll
        for (int p = 0; p < 4; p++) xp[p] = *(const ull*)&xs[k * 130 + n0 + 2 * p];
        #pragma unroll
        for (int j = 0; j < 4; j++) wd[j] = ws2[k * 64 + tx + 16 * j];
        #pragma unroll
        for (int p = 0; p < 4; p++)
            #pragma unroll
            for (int j = 0; j < 4; j++) ffma2(acc[p][j], xp[p], wd[j]);
    }

    float b1v[4], w2v[4];
    #pragma unroll
    for (int j = 0; j < 4; j++) {
        b1v[j] = b1f[fbase + tx + 16 * j];
        w2v[j] = w2[fbase + tx + 16 * j];
    }
    #pragma unroll
    for (int p = 0; p < 4; p++) {
        float slo = 0.f, shi = 0.f;
        #pragma unroll
        for (int j = 0; j < 4; j++) {
            float2 t = unpack2(acc[p][j]);
            slo += fmaxf(t.x + b1v[j], 0.f) * w2v[j];
            shi += fmaxf(t.y + b1v[j], 0.f) * w2v[j];
        }
        #pragma unroll
        for (int o = 8; o > 0; o >>= 1) {
            slo += __shfl_xor_sync(0xffffffffu, slo, o);
            shi += __shfl_xor_sync(0xffffffffu, shi, o);
        }
        if (tx == 0) {
            int n = nb + n0 + 2 * p;
            if (n < NN)     atomicAdd(&out[n], slo);
            if (n + 1 < NN) atomicAdd(&out[n + 1], shi);
        }
    }
}

__global__ void k_ssq(const float* __restrict__ out) {
    __shared__ float red[32];
    int i = blockIdx.x * 1024 + threadIdx.x;
    float v = (i < NN) ? out[i] : 0.f;
    v = v * v;
    #pragma unroll
    for (int o = 16; o > 0; o >>= 1) v += __shfl_down_sync(0xffffffffu, v, o);
    int lane = threadIdx.x & 31, wid = threadIdx.x >> 5;
    if (lane == 0) red[wid] = v;
    __syncthreads();
    if (wid == 0) {
        float w = red[lane];
        #pragma unroll
        for (int o = 16; o > 0; o >>= 1) w += __shfl_down_sync(0xffffffffu, w, o);
        if (lane == 0) atomicAdd(&g_ssq, w);
    }
}

__global__ void k_norm(float* __restrict__ out) {
    float s = 1.f / fmaxf(sqrtf(g_ssq), 1e-12f);
    int i = blockIdx.x * blockDim.x + threadIdx.x;
    if (i < NN) out[i] *= s;
}

// ---------------- launcher ----------------
extern "C" void kernel_launch(void* const* d_in, const int* in_sizes, int n_in,
                              void* d_out, int out_size) {
    const float* x    = (const float*)d_in[0];
    const int*   ei   = (const int*)d_in[1];
    const float* W1   = (const float*)d_in[2];
    const float* b1   = (const float*)d_in[3];
    const float* W2   = (const float*)d_in[4];
    const float* b2   = (const float*)d_in[5];
    const float* fc1w = (const float*)d_in[6];
    const float* fc1b = (const float*)d_in[7];
    const float* fc2w = (const float*)d_in[8];
    const float* fc2b = (const float*)d_in[9];
    float* out = (float*)d_out;

    void *p_h = nullptr, *p_hagg = nullptr;
    cudaGetSymbolAddress(&p_h, g_h);
    cudaGetSymbolAddress(&p_hagg, g_hagg);
    float* h    = (float*)p_h;
    float* hagg = (float*)p_hagg;

    const int SMEM = 8192 * 4 + 64 * 130 * 4;   // 66048 bytes
    cudaFuncSetAttribute(k_gemm, cudaFuncAttributeMaxDynamicSharedMemorySize, SMEM);
    cudaFuncSetAttribute(k_fc,   cudaFuncAttributeMaxDynamicSharedMemorySize, SMEM);

    const int nb_scan = (NN + 1023) / 1024;     // 98

    k_init<<<(NN + 255) / 256, 256>>>(out, fc2b);
    k_hist<<<(NE / 4 + 255) / 256, 256>>>(ei);
    k_scan1<<<nb_scan, 1024>>>();
    k_scan2<<<1, 128>>>(nb_scan);
    k_scan3<<<nb_scan, 1024>>>();
    k_csr<<<(NE / 4 + 255) / 256, 256>>>(ei);

    const int gemm_blocks = (NN + 127) / 128;   // 782
    const int agg_blocks  = (NN + 7) / 8;       // 12500

    k_gemm<<<gemm_blocks, 256, SMEM>>>(x, W1, h);
    k_agg<<<agg_blocks, 256>>>(h, b1, hagg);
    k_gemm<<<gemm_blocks, 256, SMEM>>>(hagg, W2, h);
    k_agg<<<agg_blocks, 256>>>(h, b2, hagg);
    k_fc<<<gemm_blocks * 4, 256, SMEM>>>(hagg, fc1w, fc1b, fc2w, out);
    k_ssq<<<nb_scan, 1024>>>(out);
    k_norm<<<(NN + 255) / 256, 256>>>(out);
}

// round 4
// speedup vs baseline: 1.0103x; 1.0103x over previous
#include <cuda_runtime.h>
#include <cstdint>

#define NN 100000
#define NE 1600000
#define DH 64
#define F1 256
#define GEMM_BLOCKS 782          // ceil(100000/128)
#define HIST_BLOCKS 1563         // ceil(400000/256)

typedef unsigned long long ull;

__device__ __forceinline__ ull pack2(float x) {
    ull r; asm("mov.b64 %0,{%1,%1};" : "=l"(r) : "f"(x)); return r;
}
__device__ __forceinline__ ull packf2(float x, float y) {
    ull r; asm("mov.b64 %0,{%1,%2};" : "=l"(r) : "f"(x), "f"(y)); return r;
}
__device__ __forceinline__ void ffma2(ull& d, ull a, ull b) {
    asm("fma.rn.f32x2 %0,%1,%2,%0;" : "+l"(d) : "l"(a), "l"(b));
}
__device__ __forceinline__ float2 unpack2(ull v) {
    float2 r; asm("mov.b64 {%0,%1},%2;" : "=f"(r.x), "=f"(r.y) : "l"(v)); return r;
}

// ---------------- scratch ----------------
__device__ int   g_deg[NN];
__device__ int   g_bsum[128];
__device__ int   g_rowptr[NN + 1];
__device__ int   g_cursor[NN];
__device__ int   g_srcidx[NE];
__device__ float g_dinv[NN];
__device__ float g_h[NN * DH];
__device__ float g_hagg[NN * DH];
__device__ float g_ssq;

// ---------------- GEMM body: out[n][f] = sum_k X[n][k]*W[k][f] (no dinv) ----------
__device__ __forceinline__ void gemm_body(const float* __restrict__ X,
                                          const float* __restrict__ W,
                                          float* __restrict__ out, int bid) {
    extern __shared__ float sm[];
    ull*   ws2 = (ull*)sm;         // [64][64] duplicated {w,w}
    float* xs  = sm + 8192;        // [64][130] x transposed
    int tid = threadIdx.x;
    int nb = bid * 128;

    for (int i = tid; i < 4096; i += 256) ws2[i] = pack2(W[i]);

    #pragma unroll
    for (int j = 0; j < 8; j++) {
        int lin = tid + j * 256;
        int n = lin >> 4, k4 = (lin & 15) * 4;
        float4 v = make_float4(0.f, 0.f, 0.f, 0.f);
        if (nb + n < NN) v = *(const float4*)&X[(size_t)(nb + n) * DH + k4];
        xs[(k4 + 0) * 130 + n] = v.x;
        xs[(k4 + 1) * 130 + n] = v.y;
        xs[(k4 + 2) * 130 + n] = v.z;
        xs[(k4 + 3) * 130 + n] = v.w;
    }
    __syncthreads();

    int tx = tid & 15, ty = tid >> 4;
    int n0 = ty * 8;
    ull acc[4][4] = {};
    #pragma unroll 16
    for (int k = 0; k < 64; k++) {
        ull xp[4], wd[4];
        #pragma unroll
        for (int p = 0; p < 4; p++) xp[p] = *(const ull*)&xs[k * 130 + n0 + 2 * p];
        #pragma unroll
        for (int j = 0; j < 4; j++) wd[j] = ws2[k * 64 + tx + 16 * j];
        #pragma unroll
        for (int p = 0; p < 4; p++)
            #pragma unroll
            for (int j = 0; j < 4; j++) ffma2(acc[p][j], xp[p], wd[j]);
    }
    #pragma unroll
    for (int p = 0; p < 4; p++) {
        int n = nb + n0 + 2 * p;
        if (n < NN) {
            bool hi = (n + 1 < NN);
            #pragma unroll
            for (int j = 0; j < 4; j++) {
                float2 t = unpack2(acc[p][j]);
                out[(size_t)n * DH + tx + 16 * j] = t.x;
                if (hi) out[(size_t)(n + 1) * DH + tx + 16 * j] = t.y;
            }
        }
    }
}

// ---------------- fused: gemm1 (blocks [0,GEMM_BLOCKS)) + histogram (rest) --------
__global__ void __launch_bounds__(256) k_histgemm(const float* __restrict__ X,
                                                  const float* __restrict__ W,
                                                  float* __restrict__ out,
                                                  const int* __restrict__ ei) {
    if (blockIdx.x < GEMM_BLOCKS) {
        gemm_body(X, W, out, blockIdx.x);
    } else {
        int e = (blockIdx.x - GEMM_BLOCKS) * 256 + threadIdx.x;
        if (e < NE / 4) {
            int4 c = ((const int4*)(ei + NE))[e];
            atomicAdd(&g_deg[c.x], 1);
            atomicAdd(&g_deg[c.y], 1);
            atomicAdd(&g_deg[c.z], 1);
            atomicAdd(&g_deg[c.w], 1);
        }
    }
}

__global__ void __launch_bounds__(256) k_gemm(const float* __restrict__ X,
                                              const float* __restrict__ W,
                                              float* __restrict__ out) {
    gemm_body(X, W, out, blockIdx.x);
}

// ---------------- scanA: per-block degree sums + out/ssq init ----------------------
__global__ void __launch_bounds__(256) k_scanA(float* __restrict__ out,
                                               const float* __restrict__ b2) {
    __shared__ int red[8];
    int tid = threadIdx.x;
    int i4 = blockIdx.x * 256 + tid;           // int4 index over 25000
    int s = 0;
    if (i4 < NN / 4) {
        int4 v = ((const int4*)g_deg)[i4];
        s = v.x + v.y + v.z + v.w;
        float b2v = b2[0];
        ((float4*)out)[i4] = make_float4(b2v, b2v, b2v, b2v);
    }
    #pragma unroll
    for (int o = 16; o > 0; o >>= 1) s += __shfl_down_sync(0xffffffffu, s, o);
    if ((tid & 31) == 0) red[tid >> 5] = s;
    __syncthreads();
    if (tid == 0) {
        int t = 0;
        #pragma unroll
        for (int w = 0; w < 8; w++) t += red[w];
        g_bsum[blockIdx.x] = t;
        if (blockIdx.x == 0) g_ssq = 0.f;
    }
}

// ---------------- scanB: rowptr/cursor/dinv -----------------------------------------
__global__ void __launch_bounds__(1024) k_scanB() {
    __shared__ int sbs[128];
    __shared__ int wsum[32];
    __shared__ int sh_base;
    int tid = threadIdx.x;
    int b = blockIdx.x;

    if (tid < 128) {
        int v = (tid < 98) ? g_bsum[tid] : 0;
        sbs[tid] = v;
        __syncwarp();
        // smem scan over 128 (done by 4 warps cooperatively via rounds)
    }
    __syncthreads();
    if (tid < 128) {
        #pragma unroll
        for (int off = 1; off < 128; off <<= 1) {
            int u = (tid >= off) ? sbs[tid - off] : 0;
            __syncthreads();
            sbs[tid] += u;
            __syncthreads();
        }
        if (tid == b) sh_base = sbs[tid] - g_bsum[tid];   // exclusive prefix of block b
    } else {
        #pragma unroll
        for (int off = 1; off < 128; off <<= 1) { __syncthreads(); __syncthreads(); }
    }
    __syncthreads();
    int base = sh_base;

    int i = b * 1024 + tid;
    int d = (i < NN) ? g_deg[i] : 0;
    // warp inclusive scan
    int incl = d;
    int lane = tid & 31, w = tid >> 5;
    #pragma unroll
    for (int o = 1; o < 32; o <<= 1) {
        int t = __shfl_up_sync(0xffffffffu, incl, o);
        if (lane >= o) incl += t;
    }
    if (lane == 31) wsum[w] = incl;
    __syncthreads();
    if (w == 0) {
        int v = wsum[lane];
        #pragma unroll
        for (int o = 1; o < 32; o <<= 1) {
            int t = __shfl_up_sync(0xffffffffu, v, o);
            if (lane >= o) v += t;
        }
        wsum[lane] = v - wsum[lane];   // exclusive warp base
    }
    __syncthreads();
    if (i < NN) {
        int excl = base + wsum[w] + incl - d;
        g_rowptr[i] = excl;
        g_cursor[i] = excl;
        g_dinv[i] = rsqrtf((float)(d + 1));
        if (i == NN - 1) g_rowptr[NN] = excl + d;
    }
}

__global__ void __launch_bounds__(256) k_csr(const int* __restrict__ ei) {
    int e = blockIdx.x * blockDim.x + threadIdx.x;
    if (e < NE / 4) {
        int4 r = ((const int4*)ei)[e];
        int4 c = ((const int4*)(ei + NE))[e];
        int p;
        p = atomicAdd(&g_cursor[c.x], 1); g_srcidx[p] = r.x;
        p = atomicAdd(&g_cursor[c.y], 1); g_srcidx[p] = r.y;
        p = atomicAdd(&g_cursor[c.z], 1); g_srcidx[p] = r.z;
        p = atomicAdd(&g_cursor[c.w], 1); g_srcidx[p] = r.w;
    }
}

// ---------------- Aggregation: out[n]=relu(dn*(dn*h[n] + sum dinv[s]*h[s]) + b) ----
__global__ void __launch_bounds__(256) k_agg(const float* __restrict__ hs,
                                             const float* __restrict__ bias,
                                             float* __restrict__ out) {
    int warp = (blockIdx.x * blockDim.x + threadIdx.x) >> 5;
    int lane = threadIdx.x & 31;
    if (warp >= NN) return;
    int n = warp;
    int f0 = lane * 2;
    float dn = g_dinv[n];

    float2 hv = *(const float2*)&hs[(size_t)n * DH + f0];
    ull acc = 0;
    ffma2(acc, packf2(hv.x, hv.y), pack2(dn));   // self term: dn*h[n]

    int beg = g_rowptr[n], end = g_rowptr[n + 1];
    for (int j = beg; j < end; j += 32) {
        int cnt = min(32, end - j);
        int s = 0; float dv = 0.f;
        if (j + lane < end) { s = g_srcidx[j + lane]; dv = g_dinv[s]; }
        #pragma unroll 4
        for (int t = 0; t < cnt; t++) {
            int   ss  = __shfl_sync(0xffffffffu, s, t);
            float dvt = __shfl_sync(0xffffffffu, dv, t);
            float2 v = *(const float2*)&hs[(size_t)ss * DH + f0];
            ffma2(acc, packf2(v.x, v.y), pack2(dvt));
        }
    }
    float2 a = unpack2(acc);
    float ox = fmaxf(fmaf(a.x, dn, bias[f0]), 0.f);
    float oy = fmaxf(fmaf(a.y, dn, bias[f0 + 1]), 0.f);
    *(float2*)&out[(size_t)n * DH + f0] = make_float2(ox, oy);
}

// ---------------- Fused MLP head as GEMM (atomic partials over 4 f-chunks) ---------
__global__ void __launch_bounds__(256) k_fc(const float* __restrict__ H,
                                            const float* __restrict__ W1f,
                                            const float* __restrict__ b1f,
                                            const float* __restrict__ w2,
                                            float* __restrict__ out) {
    extern __shared__ float sm[];
    ull*   ws2 = (ull*)sm;
    float* xs  = sm + 8192;
    int tid = threadIdx.x;
    int bid = blockIdx.x;
    int nb = (bid >> 2) * 128;
    int fbase = (bid & 3) * 64;

    for (int i = tid; i < 4096; i += 256) {
        int k = i >> 6, f = i & 63;
        ws2[i] = pack2(W1f[k * F1 + fbase + f]);
    }
    #pragma unroll
    for (int j = 0; j < 8; j++) {
        int lin = tid + j * 256;
        int n = lin >> 4, k4 = (lin & 15) * 4;
        float4 v = make_float4(0.f, 0.f, 0.f, 0.f);
        if (nb + n < NN) v = *(const float4*)&H[(size_t)(nb + n) * DH + k4];
        xs[(k4 + 0) * 130 + n] = v.x;
        xs[(k4 + 1) * 130 + n] = v.y;
        xs[(k4 + 2) * 130 + n] = v.z;
        xs[(k4 + 3) * 130 + n] = v.w;
    }
    __syncthreads();

    int tx = tid & 15, ty = tid >> 4;
    int n0 = ty * 8;
    ull acc[4][4] = {};
    #pragma unroll 16
    for (int k = 0; k < 64; k++) {
        ull xp[4], wd[4];
        #pragma unroll
        for (int p = 0; p < 4; p++) xp[p] = *(const ull*)&xs[k * 130 + n0 + 2 * p];
        #pragma unroll
        for (int j = 0; j < 4; j++) wd[j] = ws2[k * 64 + tx + 16 * j];
        #pragma unroll
        for (int p = 0; p < 4; p++)
            #pragma unroll
            for (int j = 0; j < 4; j++) ffma2(acc[p][j], xp[p], wd[j]);
    }

    float b1v[4], w2v[4];
    #pragma unroll
    for (int j = 0; j < 4; j++) {
        b1v[j] = b1f[fbase + tx + 16 * j];
        w2v[j] = w2[fbase + tx + 16 * j];
    }
    #pragma unroll
    for (int p = 0; p < 4; p++) {
        float slo = 0.f, shi = 0.f;
        #pragma unroll
        for (int j = 0; j < 4; j++) {
            float2 t = unpack2(acc[p][j]);
            slo += fmaxf(t.x + b1v[j], 0.f) * w2v[j];
            shi += fmaxf(t.y + b1v[j], 0.f) * w2v[j];
        }
        #pragma unroll
        for (int o = 8; o > 0; o >>= 1) {
            slo += __shfl_xor_sync(0xffffffffu, slo, o);
            shi += __shfl_xor_sync(0xffffffffu, shi, o);
        }
        if (tx == 0) {
            int n = nb + n0 + 2 * p;
            if (n < NN)     atomicAdd(&out[n], slo);
            if (n + 1 < NN) atomicAdd(&out[n + 1], shi);
        }
    }
}

__global__ void __launch_bounds__(1024) k_ssq(const float* __restrict__ out) {
    __shared__ float red[32];
    int i = blockIdx.x * 1024 + threadIdx.x;
    float v = (i < NN) ? out[i] : 0.f;
    v = v * v;
    #pragma unroll
    for (int o = 16; o > 0; o >>= 1) v += __shfl_down_sync(0xffffffffu, v, o);
    int lane = threadIdx.x & 31, wid = threadIdx.x >> 5;
    if (lane == 0) red[wid] = v;
    __syncthreads();
    if (wid == 0) {
        float w = red[lane];
        #pragma unroll
        for (int o = 16; o > 0; o >>= 1) w += __shfl_down_sync(0xffffffffu, w, o);
        if (lane == 0) atomicAdd(&g_ssq, w);
    }
}

__global__ void k_norm(float* __restrict__ out) {
    float s = 1.f / fmaxf(sqrtf(g_ssq), 1e-12f);
    int i = blockIdx.x * blockDim.x + threadIdx.x;
    if (i < NN) out[i] *= s;
}

// ---------------- launcher ----------------
extern "C" void kernel_launch(void* const* d_in, const int* in_sizes, int n_in,
                              void* d_out, int out_size) {
    const float* x    = (const float*)d_in[0];
    const int*   ei   = (const int*)d_in[1];
    const float* W1   = (const float*)d_in[2];
    const float* b1   = (const float*)d_in[3];
    const float* W2   = (const float*)d_in[4];
    const float* b2   = (const float*)d_in[5];
    const float* fc1w = (const float*)d_in[6];
    const float* fc1b = (const float*)d_in[7];
    const float* fc2w = (const float*)d_in[8];
    const float* fc2b = (const float*)d_in[9];
    float* out = (float*)d_out;

    void *p_h = nullptr, *p_hagg = nullptr, *p_deg = nullptr;
    cudaGetSymbolAddress(&p_h, g_h);
    cudaGetSymbolAddress(&p_hagg, g_hagg);
    cudaGetSymbolAddress(&p_deg, g_deg);
    float* h    = (float*)p_h;
    float* hagg = (float*)p_hagg;

    const int SMEM = 8192 * 4 + 64 * 130 * 4;   // 66048 bytes
    cudaFuncSetAttribute(k_histgemm, cudaFuncAttributeMaxDynamicSharedMemorySize, SMEM);
    cudaFuncSetAttribute(k_gemm,     cudaFuncAttributeMaxDynamicSharedMemorySize, SMEM);
    cudaFuncSetAttribute(k_fc,       cudaFuncAttributeMaxDynamicSharedMemorySize, SMEM);

    cudaMemsetAsync(p_deg, 0, NN * sizeof(int));

    // gemm1 (x@W1, no dinv) fused+overlapped with degree histogram
    k_histgemm<<<GEMM_BLOCKS + HIST_BLOCKS, 256, SMEM>>>(x, W1, h, ei);
    k_scanA<<<98, 256>>>(out, fc2b);     // block sums + out=b2 + ssq=0
    k_scanB<<<98, 1024>>>();             // rowptr/cursor/dinv
    k_csr<<<HIST_BLOCKS, 256>>>(ei);

    const int agg_blocks = (NN + 7) / 8;   // 12500

    k_agg<<<agg_blocks, 256>>>(h, b1, hagg);
    k_gemm<<<GEMM_BLOCKS, 256, SMEM>>>(hagg, W2, h);
    k_agg<<<agg_blocks, 256>>>(h, b2, hagg);
    k_fc<<<GEMM_BLOCKS * 4, 256, SMEM>>>(hagg, fc1w, fc1b, fc2w, out);
    k_ssq<<<98, 1024>>>(out);
    k_norm<<<(NN + 255) / 256, 256>>>(out);
}

// round 6
// speedup vs baseline: 1.2883x; 1.2751x over previous
#include <cuda_runtime.h>
#include <cuda_fp16.h>
#include <cstdint>

#define NN 100000
#define NE 1600000
#define DH 64
#define F1 256
#define GEMM_BLOCKS 782          // ceil(100000/128)
#define HIST_BLOCKS 1563         // ceil(400000/256)
#define FC_LDA 72                // A-plane stride (halves)
#define FC_LDB 264               // B-plane stride (halves)

typedef unsigned long long ull;

__device__ __forceinline__ ull pack2(float x) {
    ull r; asm("mov.b64 %0,{%1,%1};" : "=l"(r) : "f"(x)); return r;
}
__device__ __forceinline__ ull packf2(float x, float y) {
    ull r; asm("mov.b64 %0,{%1,%2};" : "=l"(r) : "f"(x), "f"(y)); return r;
}
__device__ __forceinline__ void ffma2(ull& d, ull a, ull b) {
    asm("fma.rn.f32x2 %0,%1,%2,%0;" : "+l"(d) : "l"(a), "l"(b));
}
__device__ __forceinline__ float2 unpack2(ull v) {
    float2 r; asm("mov.b64 {%0,%1},%2;" : "=f"(r.x), "=f"(r.y) : "l"(v)); return r;
}
__device__ __forceinline__ void mma16816(float* c, const unsigned* a, const unsigned* b) {
    asm volatile("mma.sync.aligned.m16n8k16.row.col.f32.f16.f16.f32 "
        "{%0,%1,%2,%3},{%4,%5,%6,%7},{%8,%9},{%0,%1,%2,%3};"
        : "+f"(c[0]), "+f"(c[1]), "+f"(c[2]), "+f"(c[3])
        : "r"(a[0]), "r"(a[1]), "r"(a[2]), "r"(a[3]), "r"(b[0]), "r"(b[1]));
}
__device__ __forceinline__ void ldsm4(unsigned* r, const void* p) {
    uint32_t a = (uint32_t)__cvta_generic_to_shared(p);
    asm volatile("ldmatrix.sync.aligned.m8n8.x4.shared.b16 {%0,%1,%2,%3},[%4];"
        : "=r"(r[0]), "=r"(r[1]), "=r"(r[2]), "=r"(r[3]) : "r"(a));
}
__device__ __forceinline__ void ldsm2t(unsigned* r, const void* p) {
    uint32_t a = (uint32_t)__cvta_generic_to_shared(p);
    asm volatile("ldmatrix.sync.aligned.m8n8.x2.trans.shared.b16 {%0,%1},[%2];"
        : "=r"(r[0]), "=r"(r[1]) : "r"(a));
}
// split x into hi+lo fp16 pair (packed half2 from two floats)
__device__ __forceinline__ void split2(float x, float y, __half2& hi, __half2& lo) {
    hi = __floats2half2_rn(x, y);
    float2 hf = __half22float2(hi);
    lo = __floats2half2_rn(x - hf.x, y - hf.y);
}

// ---------------- scratch ----------------
__device__ int    g_deg[NN];
__device__ int    g_bsum[128];
__device__ int    g_rowptr[NN + 1];
__device__ int    g_cursor[NN];
__device__ int    g_srcidx[NE];
__device__ float  g_dinv[NN];
__device__ float  g_h[NN * DH];
__device__ float  g_hagg[NN * DH];
__device__ float  g_ssq;

// ---------------- GEMM body: out[n][f] = sum_k X[n][k]*W[k][f] ----------
__device__ __forceinline__ void gemm_body(const float* __restrict__ X,
                                          const float* __restrict__ W,
                                          float* __restrict__ out, int bid) {
    extern __shared__ float sm[];
    ull*   ws2 = (ull*)sm;         // [64][64] duplicated {w,w}
    float* xs  = sm + 8192;        // [64][130] x transposed
    int tid = threadIdx.x;
    int nb = bid * 128;

    for (int i = tid; i < 4096; i += 256) ws2[i] = pack2(W[i]);

    #pragma unroll
    for (int j = 0; j < 8; j++) {
        int lin = tid + j * 256;
        int n = lin >> 4, k4 = (lin & 15) * 4;
        float4 v = make_float4(0.f, 0.f, 0.f, 0.f);
        if (nb + n < NN) v = *(const float4*)&X[(size_t)(nb + n) * DH + k4];
        xs[(k4 + 0) * 130 + n] = v.x;
        xs[(k4 + 1) * 130 + n] = v.y;
        xs[(k4 + 2) * 130 + n] = v.z;
        xs[(k4 + 3) * 130 + n] = v.w;
    }
    __syncthreads();

    int tx = tid & 15, ty = tid >> 4;
    int n0 = ty * 8;
    ull acc[4][4] = {};
    #pragma unroll 16
    for (int k = 0; k < 64; k++) {
        ull xp[4], wd[4];
        #pragma unroll
        for (int p = 0; p < 4; p++) xp[p] = *(const ull*)&xs[k * 130 + n0 + 2 * p];
        #pragma unroll
        for (int j = 0; j < 4; j++) wd[j] = ws2[k * 64 + tx + 16 * j];
        #pragma unroll
        for (int p = 0; p < 4; p++)
            #pragma unroll
            for (int j = 0; j < 4; j++) ffma2(acc[p][j], xp[p], wd[j]);
    }
    #pragma unroll
    for (int p = 0; p < 4; p++) {
        int n = nb + n0 + 2 * p;
        if (n < NN) {
            bool hi = (n + 1 < NN);
            #pragma unroll
            for (int j = 0; j < 4; j++) {
                float2 t = unpack2(acc[p][j]);
                out[(size_t)n * DH + tx + 16 * j] = t.x;
                if (hi) out[(size_t)(n + 1) * DH + tx + 16 * j] = t.y;
            }
        }
    }
}

// ---------------- fused: gemm1 + histogram --------
__global__ void __launch_bounds__(256) k_histgemm(const float* __restrict__ X,
                                                  const float* __restrict__ W,
                                                  float* __restrict__ out,
                                                  const int* __restrict__ ei) {
    if (blockIdx.x < GEMM_BLOCKS) {
        gemm_body(X, W, out, blockIdx.x);
    } else {
        int e = (blockIdx.x - GEMM_BLOCKS) * 256 + threadIdx.x;
        if (e < NE / 4) {
            int4 c = ((const int4*)(ei + NE))[e];
            atomicAdd(&g_deg[c.x], 1);
            atomicAdd(&g_deg[c.y], 1);
            atomicAdd(&g_deg[c.z], 1);
            atomicAdd(&g_deg[c.w], 1);
        }
    }
}

__global__ void __launch_bounds__(256) k_gemm(const float* __restrict__ X,
                                              const float* __restrict__ W,
                                              float* __restrict__ out) {
    gemm_body(X, W, out, blockIdx.x);
}

// ---------------- scanA: per-block degree sums + ssq init ----------------------
__global__ void __launch_bounds__(256) k_scanA() {
    __shared__ int red[8];
    int tid = threadIdx.x;
    int i4 = blockIdx.x * 256 + tid;
    int s = 0;
    if (i4 < NN / 4) {
        int4 v = ((const int4*)g_deg)[i4];
        s = v.x + v.y + v.z + v.w;
    }
    #pragma unroll
    for (int o = 16; o > 0; o >>= 1) s += __shfl_down_sync(0xffffffffu, s, o);
    if ((tid & 31) == 0) red[tid >> 5] = s;
    __syncthreads();
    if (tid == 0) {
        int t = 0;
        #pragma unroll
        for (int w = 0; w < 8; w++) t += red[w];
        g_bsum[blockIdx.x] = t;
        if (blockIdx.x == 0) g_ssq = 0.f;
    }
}

// ---------------- scanB: rowptr/cursor/dinv -----------------------------------------
__global__ void __launch_bounds__(1024) k_scanB() {
    __shared__ int sbs[128];
    __shared__ int wsum[32];
    __shared__ int sh_base;
    int tid = threadIdx.x;
    int b = blockIdx.x;

    if (tid < 128) {
        int v = (tid < 98) ? g_bsum[tid] : 0;
        sbs[tid] = v;
    }
    __syncthreads();
    if (tid < 128) {
        #pragma unroll
        for (int off = 1; off < 128; off <<= 1) {
            int u = (tid >= off) ? sbs[tid - off] : 0;
            __syncthreads();
            sbs[tid] += u;
            __syncthreads();
        }
        if (tid == b) sh_base = sbs[tid] - g_bsum[tid];
    } else {
        #pragma unroll
        for (int off = 1; off < 128; off <<= 1) { __syncthreads(); __syncthreads(); }
    }
    __syncthreads();
    int base = sh_base;

    int i = b * 1024 + tid;
    int d = (i < NN) ? g_deg[i] : 0;
    int incl = d;
    int lane = tid & 31, w = tid >> 5;
    #pragma unroll
    for (int o = 1; o < 32; o <<= 1) {
        int t = __shfl_up_sync(0xffffffffu, incl, o);
        if (lane >= o) incl += t;
    }
    if (lane == 31) wsum[w] = incl;
    __syncthreads();
    if (w == 0) {
        int v = wsum[lane];
        #pragma unroll
        for (int o = 1; o < 32; o <<= 1) {
            int t = __shfl_up_sync(0xffffffffu, v, o);
            if (lane >= o) v += t;
        }
        wsum[lane] = v - wsum[lane];
    }
    __syncthreads();
    if (i < NN) {
        int excl = base + wsum[w] + incl - d;
        g_rowptr[i] = excl;
        g_cursor[i] = excl;
        g_dinv[i] = rsqrtf((float)(d + 1));
        if (i == NN - 1) g_rowptr[NN] = excl + d;
    }
}

__global__ void __launch_bounds__(256) k_csr(const int* __restrict__ ei) {
    int e = blockIdx.x * blockDim.x + threadIdx.x;
    if (e < NE / 4) {
        int4 r = ((const int4*)ei)[e];
        int4 c = ((const int4*)(ei + NE))[e];
        int p;
        p = atomicAdd(&g_cursor[c.x], 1); g_srcidx[p] = r.x;
        p = atomicAdd(&g_cursor[c.y], 1); g_srcidx[p] = r.y;
        p = atomicAdd(&g_cursor[c.z], 1); g_srcidx[p] = r.z;
        p = atomicAdd(&g_cursor[c.w], 1); g_srcidx[p] = r.w;
    }
}

// ---------------- Aggregation: out[n]=relu(dn*(dn*h[n] + sum dinv[s]*h[s]) + b) ----
__global__ void __launch_bounds__(256) k_agg32(const float* __restrict__ hs,
                                               const float* __restrict__ bias,
                                               float* __restrict__ out) {
    int warp = (blockIdx.x * blockDim.x + threadIdx.x) >> 5;
    int lane = threadIdx.x & 31;
    if (warp >= NN) return;
    int n = warp;
    int f0 = lane * 2;
    float dn = g_dinv[n];

    float2 hv = *(const float2*)&hs[(size_t)n * DH + f0];
    ull acc = 0;
    ffma2(acc, packf2(hv.x, hv.y), pack2(dn));

    int beg = g_rowptr[n], end = g_rowptr[n + 1];
    for (int j = beg; j < end; j += 32) {
        int cnt = min(32, end - j);
        int s = 0; float dv = 0.f;
        if (j + lane < end) { s = g_srcidx[j + lane]; dv = g_dinv[s]; }
        #pragma unroll 4
        for (int t = 0; t < cnt; t++) {
            int   ss  = __shfl_sync(0xffffffffu, s, t);
            float dvt = __shfl_sync(0xffffffffu, dv, t);
            float2 v = *(const float2*)&hs[(size_t)ss * DH + f0];
            ffma2(acc, packf2(v.x, v.y), pack2(dvt));
        }
    }
    float2 a = unpack2(acc);
    float ox = fmaxf(fmaf(a.x, dn, bias[f0]), 0.f);
    float oy = fmaxf(fmaf(a.y, dn, bias[f0 + 1]), 0.f);
    *(float2*)&out[(size_t)n * DH + f0] = make_float2(ox, oy);
}

// ---------------- MLP head: split-fp16 3-pass HMMA, fp32-exact -----------------------
// Block = 128 nodes x full 256 fc1 features. 8 warps: warp w -> 16 nodes.
// C = Ahi*Bhi + Alo*Bhi + Ahi*Blo (fp32 accum). Epilogue relu(+b1)*w2 reduce,
// direct store + block-level ssq atomicAdd.
__global__ void __launch_bounds__(256) k_fcmma(const float* __restrict__ H,
                                               const float* __restrict__ W1f,
                                               const float* __restrict__ b1f,
                                               const float* __restrict__ w2,
                                               const float* __restrict__ b2,
                                               float* __restrict__ out) {
    extern __shared__ char smc[];
    __half* Bhi = (__half*)smc;                                    // [64][FC_LDB]
    __half* Blo = Bhi + 64 * FC_LDB;
    __half* Ahi = Blo + 64 * FC_LDB;                               // [128][FC_LDA]
    __half* Alo = Ahi + 128 * FC_LDA;
    float*  b1s = (float*)(Alo + 128 * FC_LDA);
    float*  w2s = b1s + F1;
    float*  sred = w2s + F1;                                       // [8]

    int tid = threadIdx.x;
    int nb = blockIdx.x * 128;

    // fc1w (64x256 fp32) -> hi/lo fp16 planes
    const float2* Wv = (const float2*)W1f;
    #pragma unroll
    for (int j = 0; j < 32; j++) {
        int f2 = tid + j * 256;          // 8192 float2
        int k = f2 >> 7, n = (f2 & 127) * 2;
        float2 v = Wv[f2];
        __half2 hi, lo; split2(v.x, v.y, hi, lo);
        *(__half2*)&Bhi[k * FC_LDB + n] = hi;
        *(__half2*)&Blo[k * FC_LDB + n] = lo;
    }
    b1s[tid] = b1f[tid];
    w2s[tid] = w2[tid];

    // H tile (fp32) -> hi/lo fp16 planes
    #pragma unroll
    for (int j = 0; j < 8; j++) {
        int t = tid + j * 256;           // 2048 float4
        int r = t >> 4, c4 = (t & 15) * 4;
        float4 v = make_float4(0.f, 0.f, 0.f, 0.f);
        if (nb + r < NN) v = *(const float4*)&H[(size_t)(nb + r) * DH + c4];
        __half2 hi0, lo0, hi1, lo1;
        split2(v.x, v.y, hi0, lo0);
        split2(v.z, v.w, hi1, lo1);
        *(__half2*)&Ahi[r * FC_LDA + c4]     = hi0;
        *(__half2*)&Ahi[r * FC_LDA + c4 + 2] = hi1;
        *(__half2*)&Alo[r * FC_LDA + c4]     = lo0;
        *(__half2*)&Alo[r * FC_LDA + c4 + 2] = lo1;
    }
    __syncthreads();

    int lane = tid & 31, w = tid >> 5;
    int row0 = w * 16;

    unsigned ahi[4][4], alo[4][4];
    #pragma unroll
    for (int ks = 0; ks < 4; ks++) {
        int off = (row0 + (lane & 15)) * FC_LDA + (lane >> 4) * 8 + ks * 16;
        ldsm4(ahi[ks], &Ahi[off]);
        ldsm4(alo[ks], &Alo[off]);
    }

    float b2v = b2[0];
    float s0 = 0.f, s1 = 0.f;
    #pragma unroll
    for (int n8 = 0; n8 < 32; n8++) {
        int n0 = n8 * 8;
        float c[4] = {0.f, 0.f, 0.f, 0.f};
        #pragma unroll
        for (int ks = 0; ks < 4; ks++) {
            int roff = ((lane & 15) + ks * 16) * FC_LDB + n0;
            unsigned bh[2], bl[2];
            ldsm2t(bh, &Bhi[roff]);
            ldsm2t(bl, &Blo[roff]);
            mma16816(c, ahi[ks], bh);
            mma16816(c, alo[ks], bh);
            mma16816(c, ahi[ks], bl);
        }
        int col = n0 + (lane & 3) * 2;
        float2 bb = *(const float2*)&b1s[col];
        float2 ww = *(const float2*)&w2s[col];
        s0 += fmaxf(c[0] + bb.x, 0.f) * ww.x + fmaxf(c[1] + bb.y, 0.f) * ww.y;
        s1 += fmaxf(c[2] + bb.x, 0.f) * ww.x + fmaxf(c[3] + bb.y, 0.f) * ww.y;
    }
    s0 += __shfl_xor_sync(0xffffffffu, s0, 1);
    s0 += __shfl_xor_sync(0xffffffffu, s0, 2);
    s1 += __shfl_xor_sync(0xffffffffu, s1, 1);
    s1 += __shfl_xor_sync(0xffffffffu, s1, 2);

    // stores + local ssq
    float lsq = 0.f;
    if ((lane & 3) == 0) {
        int n = nb + row0 + (lane >> 2);
        float o0 = s0 + b2v, o1 = s1 + b2v;
        if (n < NN)     { out[n] = o0;     lsq += o0 * o0; }
        if (n + 8 < NN) { out[n + 8] = o1; lsq += o1 * o1; }
    }
    #pragma unroll
    for (int o = 16; o > 0; o >>= 1) lsq += __shfl_down_sync(0xffffffffu, lsq, o);
    if (lane == 0) sred[w] = lsq;
    __syncthreads();
    if (tid == 0) {
        float t = 0.f;
        #pragma unroll
        for (int q = 0; q < 8; q++) t += sred[q];
        atomicAdd(&g_ssq, t);
    }
}

__global__ void k_norm(float* __restrict__ out) {
    float s = 1.f / fmaxf(sqrtf(g_ssq), 1e-12f);
    int i = blockIdx.x * blockDim.x + threadIdx.x;
    if (i < NN) out[i] *= s;
}

// ---------------- launcher ----------------
extern "C" void kernel_launch(void* const* d_in, const int* in_sizes, int n_in,
                              void* d_out, int out_size) {
    const float* x    = (const float*)d_in[0];
    const int*   ei   = (const int*)d_in[1];
    const float* W1   = (const float*)d_in[2];
    const float* b1   = (const float*)d_in[3];
    const float* W2   = (const float*)d_in[4];
    const float* b2   = (const float*)d_in[5];
    const float* fc1w = (const float*)d_in[6];
    const float* fc1b = (const float*)d_in[7];
    const float* fc2w = (const float*)d_in[8];
    const float* fc2b = (const float*)d_in[9];
    float* out = (float*)d_out;

    void *p_h = nullptr, *p_hagg = nullptr, *p_deg = nullptr;
    cudaGetSymbolAddress(&p_h, g_h);
    cudaGetSymbolAddress(&p_hagg, g_hagg);
    cudaGetSymbolAddress(&p_deg, g_deg);
    float* h    = (float*)p_h;
    float* hagg = (float*)p_hagg;

    const int SMEM = 8192 * 4 + 64 * 130 * 4;   // 66048 (gemm)
    // fc: B planes 2*64*264*2 + A planes 2*128*72*2 + b1/w2 2*256*4 + sred 32
    const int SMEM_FC = 2 * 64 * FC_LDB * 2 + 2 * 128 * FC_LDA * 2 + 2 * F1 * 4 + 32;
    cudaFuncSetAttribute(k_histgemm, cudaFuncAttributeMaxDynamicSharedMemorySize, SMEM);
    cudaFuncSetAttribute(k_gemm,     cudaFuncAttributeMaxDynamicSharedMemorySize, SMEM);
    cudaFuncSetAttribute(k_fcmma,    cudaFuncAttributeMaxDynamicSharedMemorySize, SMEM_FC);

    cudaMemsetAsync(p_deg, 0, NN * sizeof(int));

    k_histgemm<<<GEMM_BLOCKS + HIST_BLOCKS, 256, SMEM>>>(x, W1, h, ei);
    k_scanA<<<98, 256>>>();
    k_scanB<<<98, 1024>>>();
    k_csr<<<HIST_BLOCKS, 256>>>(ei);

    const int agg_blocks = (NN + 7) / 8;   // 12500

    k_agg32<<<agg_blocks, 256>>>(h, b1, hagg);
    k_gemm<<<GEMM_BLOCKS, 256, SMEM>>>(hagg, W2, h);
    k_agg32<<<agg_blocks, 256>>>(h, b2, hagg);
    k_fcmma<<<GEMM_BLOCKS, 256, SMEM_FC>>>(hagg, fc1w, fc1b, fc2w, fc2b, out);
    k_norm<<<(NN + 255) / 256, 256>>>(out);
}